// round 1
// baseline (speedup 1.0000x reference)
#include <cuda_runtime.h>
#include <cstdint>
#include <cstddef>

// Problem constants (fixed shapes).
#define MM 8192     // B*S tokens
#define NN 11008    // OUT
#define KK 4096     // IN
#define GG 32       // groups (IN/128)

#define BM 128
#define BN 128
#define BK 32
#define STRIDE 36   // BK + 4 pad: bank = 4*(lane/4)+lane%4 -> conflict-free frag LDS
#define THREADS 256

__device__ __forceinline__ float to_tf32(float x) {
    float r;
    asm("cvt.rna.tf32.f32 %0, %1;" : "=f"(r) : "f"(x));
    return r;
}

__device__ __forceinline__ void mma_m16n8k8(float* c, const float* a, const float* b) {
    const uint32_t* A = reinterpret_cast<const uint32_t*>(a);
    const uint32_t* B = reinterpret_cast<const uint32_t*>(b);
    asm volatile(
        "mma.sync.aligned.m16n8k8.row.col.f32.tf32.tf32.f32 "
        "{%0,%1,%2,%3}, {%4,%5,%6,%7}, {%8,%9}, {%0,%1,%2,%3};\n"
        : "+f"(c[0]), "+f"(c[1]), "+f"(c[2]), "+f"(c[3])
        : "r"(A[0]), "r"(A[1]), "r"(A[2]), "r"(A[3]),
          "r"(B[0]), "r"(B[1]));
}

__global__ __launch_bounds__(THREADS, 1)
void quarot_tf32_gemm(const float* __restrict__ X,    // [M, K]
                      const float* __restrict__ SX,   // [M]
                      const float* __restrict__ W,    // [N, K]
                      const float* __restrict__ WS,   // [N, G]
                      const float* __restrict__ OFF,  // [N, G]
                      float* __restrict__ OUT)        // [M, N]
{
    extern __shared__ float smem[];
    float* As = smem;                         // [2][BM][STRIDE]
    float* Bs = smem + 2 * BM * STRIDE;       // [2][BN][STRIDE]

    const int tid  = threadIdx.x;
    const int lane = tid & 31;
    const int warp = tid >> 5;
    const int wm0  = (warp >> 2) * 64;   // warp rows: 2 warps in m
    const int wn0  = (warp & 3) * 32;    // warp cols: 4 warps in n

    const int m0 = blockIdx.y * BM;
    const int n0 = blockIdx.x * BN;

    // Global-load assignment: 2 threads per tile row, 4 float4 each (32 floats/row).
    const int ldrow = tid >> 1;           // 0..127
    const int ldseg = (tid & 1) * 16;     // float offset within row: 0 or 16

    const float* Xrow = X + (size_t)(m0 + ldrow) * KK;
    const float* Wrow = W + (size_t)(n0 + ldrow) * KK;
    const float* WSrow  = WS  + (size_t)(n0 + ldrow) * GG;
    const float* OFFrow = OFF + (size_t)(n0 + ldrow) * GG;

    float acc[4][4][4];
    #pragma unroll
    for (int i = 0; i < 4; i++)
        #pragma unroll
        for (int j = 0; j < 4; j++)
            #pragma unroll
            for (int c = 0; c < 4; c++) acc[i][j][c] = 0.f;

    float4 ra[4], rb[4];
    float ws, off;

    auto ldg_tile = [&](int kt) {
        const int k0 = kt * BK;
        #pragma unroll
        for (int j = 0; j < 4; j++)
            ra[j] = *reinterpret_cast<const float4*>(Xrow + k0 + ldseg + 4 * j);
        #pragma unroll
        for (int j = 0; j < 4; j++)
            rb[j] = *reinterpret_cast<const float4*>(Wrow + k0 + ldseg + 4 * j);
        const int g = k0 >> 7;   // group constant within a BK=32 tile (32 | 128)
        ws  = WSrow[g];
        off = OFFrow[g];
    };

    auto sts_tile = [&](int p) {
        float* Ap = As + p * BM * STRIDE + ldrow * STRIDE + ldseg;
        float* Bp = Bs + p * BN * STRIDE + ldrow * STRIDE + ldseg;
        #pragma unroll
        for (int j = 0; j < 4; j++) {
            float4 va, vb;
            va.x = to_tf32(ra[j].x); va.y = to_tf32(ra[j].y);
            va.z = to_tf32(ra[j].z); va.w = to_tf32(ra[j].w);
            vb.x = to_tf32((rb[j].x - off) * ws);
            vb.y = to_tf32((rb[j].y - off) * ws);
            vb.z = to_tf32((rb[j].z - off) * ws);
            vb.w = to_tf32((rb[j].w - off) * ws);
            *reinterpret_cast<float4*>(Ap + 4 * j) = va;
            *reinterpret_cast<float4*>(Bp + 4 * j) = vb;
        }
    };

    const int lr = lane >> 2;   // 0..7
    const int lc = lane & 3;    // 0..3

    auto compute = [&](int p) {
        const float* Ap = As + p * BM * STRIDE;
        const float* Bp = Bs + p * BN * STRIDE;
        #pragma unroll
        for (int kk = 0; kk < 4; kk++) {
            const int k = kk * 8 + lc;
            float a[4][4], b[4][2];
            #pragma unroll
            for (int mi = 0; mi < 4; mi++) {
                const float* base = Ap + (wm0 + mi * 16 + lr) * STRIDE + k;
                a[mi][0] = base[0];
                a[mi][1] = base[8 * STRIDE];
                a[mi][2] = base[4];
                a[mi][3] = base[8 * STRIDE + 4];
            }
            #pragma unroll
            for (int ni = 0; ni < 4; ni++) {
                const float* base = Bp + (wn0 + ni * 8 + lr) * STRIDE + k;
                b[ni][0] = base[0];
                b[ni][1] = base[4];
            }
            #pragma unroll
            for (int mi = 0; mi < 4; mi++)
                #pragma unroll
                for (int ni = 0; ni < 4; ni++)
                    mma_m16n8k8(acc[mi][ni], a[mi], b[ni]);
        }
    };

    ldg_tile(0);
    sts_tile(0);
    __syncthreads();

    const int KT = KK / BK;   // 128
    for (int kt = 0; kt < KT; kt++) {
        const int p = kt & 1;
        if (kt + 1 < KT) ldg_tile(kt + 1);
        compute(p);
        if (kt + 1 < KT) {
            sts_tile(p ^ 1);
            __syncthreads();
        }
    }

    // Epilogue: fold per-token activation scale, write float2.
    #pragma unroll
    for (int mi = 0; mi < 4; mi++) {
        const int r0 = m0 + wm0 + mi * 16 + lr;
        const float s0 = SX[r0];
        const float s1 = SX[r0 + 8];
        #pragma unroll
        for (int ni = 0; ni < 4; ni++) {
            const int col = n0 + wn0 + ni * 8 + lc * 2;
            float2 v0, v1;
            v0.x = acc[mi][ni][0] * s0; v0.y = acc[mi][ni][1] * s0;
            v1.x = acc[mi][ni][2] * s1; v1.y = acc[mi][ni][3] * s1;
            *reinterpret_cast<float2*>(OUT + (size_t)r0 * NN + col)       = v0;
            *reinterpret_cast<float2*>(OUT + (size_t)(r0 + 8) * NN + col) = v1;
        }
    }
}

extern "C" void kernel_launch(void* const* d_in, const int* in_sizes, int n_in,
                              void* d_out, int out_size) {
    const float* X   = (const float*)d_in[0];   // quantized_x [B,S,IN]
    const float* SX  = (const float*)d_in[1];   // scales_x    [B,S,1]
    const float* W   = (const float*)d_in[2];   // weight      [OUT,IN]
    const float* WS  = (const float*)d_in[3];   // weight_scales [OUT,G]
    const float* OFF = (const float*)d_in[4];   // offset_w    [OUT,G]
    float* OUT = (float*)d_out;

    const size_t smem_bytes = (size_t)4 * BM * STRIDE * sizeof(float) * 2; // A+B, 2 bufs
    // 73728 B > 48 KB default: opt in. First (non-captured) correctness call sets
    // this persistently; subsequent capture-time calls are idempotent.
    cudaFuncSetAttribute(quarot_tf32_gemm,
                         cudaFuncAttributeMaxDynamicSharedMemorySize,
                         (int)smem_bytes);

    dim3 grid(NN / BN, MM / BM);   // (86, 64)
    quarot_tf32_gemm<<<grid, THREADS, smem_bytes>>>(X, SX, W, WS, OFF, OUT);
}

// round 4
// speedup vs baseline: 1.1384x; 1.1384x over previous
#include <cuda_runtime.h>
#include <cstdint>
#include <cstddef>

// ---- problem shapes ----
#define MM 8192
#define NN 11008
#define KK 4096
#define GG 32

// ---- GEMM tiling ----
#define BM 128
#define BN 256
#define BK 32
#define STAGES 4
#define KT (KK / BK)               // 128
#define THREADS 256

#define NB (NN / BN)               // 43
#define MB (MM / BM)               // 64

// packed A: [mb][kt][kt2(4)][mt(8)][lane(32)][4 floats]  -> 4096 floats per (mb,kt)
#define A_STEP 4096
// packed B: [nb][kt][kt2(4)][nt(32)][lane(32)][2 floats] -> 8192 floats per (nb,kt)
#define B_STEP 8192

#define STAGE_FLOATS (A_STEP + B_STEP)              // 12288
#define STAGE_BYTES  (STAGE_FLOATS * 4)             // 49152
#define SMEM_TOTAL   (STAGES * STAGE_BYTES)         // 196608 (192 KB)

// ---- scratch (device globals are the sanctioned no-alloc scratch) ----
__device__ __align__(256) float g_Xa[(size_t)MM * KK];   // fragment-packed A
__device__ __align__(256) float g_Wb[(size_t)NN * KK];   // fragment-packed dequant W

// ---------------- helpers ----------------
__device__ __forceinline__ float to_tf32(float x) {
    float r;
    asm("cvt.rna.tf32.f32 %0, %1;" : "=f"(r) : "f"(x));
    return r;
}
__device__ __forceinline__ uint32_t smem_u32(const void* p) {
    uint32_t a;
    asm("{ .reg .u64 t; cvta.to.shared.u64 t, %1; cvt.u32.u64 %0, t; }"
        : "=r"(a) : "l"(p));
    return a;
}
__device__ __forceinline__ void cp16(uint32_t s, const void* g) {
    asm volatile("cp.async.cg.shared.global [%0], [%1], 16;" :: "r"(s), "l"(g));
}
__device__ __forceinline__ void cp_commit() {
    asm volatile("cp.async.commit_group;" ::: "memory");
}
__device__ __forceinline__ void cp_wait2() {
    asm volatile("cp.async.wait_group 2;" ::: "memory");
}
__device__ __forceinline__ void cp_wait1() {
    asm volatile("cp.async.wait_group 1;" ::: "memory");
}
__device__ __forceinline__ void cp_wait0() {
    asm volatile("cp.async.wait_group 0;" ::: "memory");
}
__device__ __forceinline__ void mma_m16n8k8(float* c, const float* a, const float* b) {
    const uint32_t* A = reinterpret_cast<const uint32_t*>(a);
    const uint32_t* B = reinterpret_cast<const uint32_t*>(b);
    asm volatile(
        "mma.sync.aligned.m16n8k8.row.col.f32.tf32.tf32.f32 "
        "{%0,%1,%2,%3}, {%4,%5,%6,%7}, {%8,%9}, {%0,%1,%2,%3};\n"
        : "+f"(c[0]), "+f"(c[1]), "+f"(c[2]), "+f"(c[3])
        : "r"(A[0]), "r"(A[1]), "r"(A[2]), "r"(A[3]),
          "r"(B[0]), "r"(B[1]));
}

// ---------------- prepass: X * sx -> fragment-packed tf32 ----------------
// tile index t = ((mb*KT + kt)*4 + kt2)*8 + mt ; one warp per tile.
// lane l writes [A[r][c], A[r+8][c], A[r][c+4], A[r+8][c+4]] at t*128 + l*4.
__global__ void prep_x(const float* __restrict__ X, const float* __restrict__ SX) {
    const int tiles = MB * KT * 4 * 8;   // 262144
    const int lane = threadIdx.x & 31;
    const int gw = (blockIdx.x * blockDim.x + threadIdx.x) >> 5;
    const int nw = (gridDim.x * blockDim.x) >> 5;
    for (int t = gw; t < tiles; t += nw) {
        const int mt  = t & 7;
        const int kt2 = (t >> 3) & 3;
        const int kt  = (t >> 5) & 127;
        const int mb  = t >> 12;
        const int r = mb * BM + mt * 16 + (lane >> 2);
        const int c = kt * BK + kt2 * 8 + (lane & 3);
        const float s0 = __ldg(SX + r);
        const float s1 = __ldg(SX + r + 8);
        float4 v;
        v.x = to_tf32(__ldg(X + (size_t)r * KK + c) * s0);
        v.y = to_tf32(__ldg(X + (size_t)(r + 8) * KK + c) * s1);
        v.z = to_tf32(__ldg(X + (size_t)r * KK + c + 4) * s0);
        v.w = to_tf32(__ldg(X + (size_t)(r + 8) * KK + c + 4) * s1);
        *reinterpret_cast<float4*>(g_Xa + (size_t)t * 128 + lane * 4) = v;
    }
}

// ---------------- prepass: (W - off) * ws -> fragment-packed tf32 ----------------
// tile index t = ((nb*KT + kt)*4 + kt2)*32 + nt ; lane l writes
// [(W[n][k]-off)*ws, (W[n][k+4]-off)*ws] at t*64 + l*2, n = base + l/4, k = base + l%4.
__global__ void prep_w(const float* __restrict__ W, const float* __restrict__ WS,
                       const float* __restrict__ OFF) {
    const int tiles = NB * KT * 4 * 32;  // 704512
    const int lane = threadIdx.x & 31;
    const int gw = (blockIdx.x * blockDim.x + threadIdx.x) >> 5;
    const int nw = (gridDim.x * blockDim.x) >> 5;
    for (int t = gw; t < tiles; t += nw) {
        const int nt  = t & 31;
        const int kt2 = (t >> 5) & 3;
        const int kt  = (t >> 7) & 127;
        const int nb  = t >> 14;
        const int n = nb * BN + nt * 8 + (lane >> 2);
        const int k = kt * BK + kt2 * 8 + (lane & 3);
        const int g = k >> 7;                       // k and k+4 share the group
        const float ws  = __ldg(WS + (size_t)n * GG + g);
        const float off = __ldg(OFF + (size_t)n * GG + g);
        float2 v;
        v.x = to_tf32((__ldg(W + (size_t)n * KK + k) - off) * ws);
        v.y = to_tf32((__ldg(W + (size_t)n * KK + k + 4) - off) * ws);
        *reinterpret_cast<float2*>(g_Wb + (size_t)t * 64 + lane * 2) = v;
    }
}

// ---------------- GEMM: fragment-packed tf32 mma.sync ----------------
__global__ __launch_bounds__(THREADS, 1)
void gemm_frag(float* __restrict__ OUT) {
    extern __shared__ float smem[];
    const uint32_t sbase = smem_u32(smem);

    const int tid = threadIdx.x;
    const int wid = tid >> 5;
    const int lane = tid & 31;
    const int wm = wid >> 2;        // 0..1  (M half)
    const int wn = wid & 3;         // 0..3  (N quarter)

    // CTA swizzle: groups of 8 mb per nb sweep -> wave working set fits L2.
    const int bid = blockIdx.x;
    const int grp = bid / (8 * NB);
    const int rem = bid - grp * (8 * NB);
    const int mb = grp * 8 + (rem & 7);
    const int nb = rem >> 3;

    const float* Ag = g_Xa + (size_t)mb * KT * A_STEP;
    const float* Bg = g_Wb + (size_t)nb * KT * B_STEP;

    float acc[4][8][4];
    #pragma unroll
    for (int i = 0; i < 4; i++)
        #pragma unroll
        for (int j = 0; j < 8; j++)
            #pragma unroll
            for (int c = 0; c < 4; c++) acc[i][j][c] = 0.f;

    auto load_stage = [&](int s, int kt) {
        const uint32_t sa = sbase + s * STAGE_BYTES;
        const float* a = Ag + (size_t)kt * A_STEP + tid * 16;   // 64 B / thread
        #pragma unroll
        for (int j = 0; j < 4; j++) cp16(sa + tid * 64 + j * 16, a + j * 4);
        const uint32_t sbb = sa + A_STEP * 4;
        const float* b = Bg + (size_t)kt * B_STEP + tid * 32;   // 128 B / thread
        #pragma unroll
        for (int j = 0; j < 8; j++) cp16(sbb + tid * 128 + j * 16, b + j * 4);
        cp_commit();
    };

    auto compute = [&](int s) {
        const float* As = smem + s * STAGE_FLOATS;
        const float* Bs = As + A_STEP;
        #pragma unroll
        for (int kt2 = 0; kt2 < 4; kt2++) {
            float4 af[4];
            #pragma unroll
            for (int mi = 0; mi < 4; mi++) {
                const int mt = wm * 4 + mi;
                af[mi] = *reinterpret_cast<const float4*>(
                    As + ((kt2 * 8 + mt) * 32 + lane) * 4);
            }
            float2 bf[8];
            #pragma unroll
            for (int ni = 0; ni < 8; ni++) {
                const int nt = wn * 8 + ni;
                bf[ni] = *reinterpret_cast<const float2*>(
                    Bs + ((kt2 * 32 + nt) * 32 + lane) * 2);
            }
            #pragma unroll
            for (int mi = 0; mi < 4; mi++)
                #pragma unroll
                for (int ni = 0; ni < 8; ni++)
                    mma_m16n8k8(acc[mi][ni],
                                reinterpret_cast<const float*>(&af[mi]),
                                reinterpret_cast<const float*>(&bf[ni]));
        }
    };

    load_stage(0, 0);
    load_stage(1, 1);
    load_stage(2, 2);

    for (int kt = 0; kt < KT; kt++) {
        if (kt < KT - 2)      cp_wait2();
        else if (kt == KT - 2) cp_wait1();
        else                   cp_wait0();
        __syncthreads();
        if (kt + 3 < KT) load_stage((kt + 3) & 3, kt + 3);
        compute(kt & 3);
    }

    // epilogue
    const int m0 = mb * BM + wm * 64;
    const int n0 = nb * BN + wn * 64;
    #pragma unroll
    for (int mi = 0; mi < 4; mi++) {
        const int row = m0 + mi * 16 + (lane >> 2);
        #pragma unroll
        for (int ni = 0; ni < 8; ni++) {
            const int col = n0 + ni * 8 + (lane & 3) * 2;
            float2 v0, v1;
            v0.x = acc[mi][ni][0]; v0.y = acc[mi][ni][1];
            v1.x = acc[mi][ni][2]; v1.y = acc[mi][ni][3];
            *reinterpret_cast<float2*>(OUT + (size_t)row * NN + col)       = v0;
            *reinterpret_cast<float2*>(OUT + (size_t)(row + 8) * NN + col) = v1;
        }
    }
}

// ---------------- launch ----------------
extern "C" void kernel_launch(void* const* d_in, const int* in_sizes, int n_in,
                              void* d_out, int out_size) {
    const float* X   = (const float*)d_in[0];
    const float* SX  = (const float*)d_in[1];
    const float* W   = (const float*)d_in[2];
    const float* WS  = (const float*)d_in[3];
    const float* OFF = (const float*)d_in[4];
    float* OUT = (float*)d_out;

    cudaFuncSetAttribute(gemm_frag,
                         cudaFuncAttributeMaxDynamicSharedMemorySize, SMEM_TOTAL);

    prep_x<<<2048, 256>>>(X, SX);
    prep_w<<<2048, 256>>>(W, WS, OFF);

    gemm_frag<<<MB * NB, THREADS, SMEM_TOTAL>>>(OUT);
}

// round 5
// speedup vs baseline: 2.8377x; 2.4928x over previous
#include <cuda_runtime.h>
#include <cuda_fp16.h>
#include <cstdint>
#include <cstddef>

// ---- problem shapes ----
#define MM 8192
#define NN 11008
#define KK 4096
#define GG 32

// ---- GEMM tiling ----
#define BM 128
#define BN 256
#define BK 32
#define STAGES 4
#define KT (KK / BK)               // 128
#define THREADS 256

#define NB (NN / BN)               // 43
#define MB (MM / BM)               // 64

// packed A (fp16): per (mb,kt): kt2(2) x mt(8) tiles of 16x16, 256 halves each
#define A_HALVES 4096              // per (mb,kt)  -> 8 KB
#define A_BYTES  (A_HALVES * 2)
// packed B (fp16): per (nb,kt): kt2(2) x nt(32) tiles of 8x16, 128 halves each
#define B_HALVES 8192              // per (nb,kt)  -> 16 KB
#define B_BYTES  (B_HALVES * 2)

#define STAGE_BYTES (A_BYTES + B_BYTES)         // 24576
#define SMEM_TOTAL  (STAGES * STAGE_BYTES)      // 98304

// ---- scratch ----
__device__ __align__(256) __half g_Xa[(size_t)MM * KK];
__device__ __align__(256) __half g_Wb[(size_t)NN * KK];

// ---------------- helpers ----------------
__device__ __forceinline__ uint32_t smem_u32(const void* p) {
    uint32_t a;
    asm("{ .reg .u64 t; cvta.to.shared.u64 t, %1; cvt.u32.u64 %0, t; }"
        : "=r"(a) : "l"(p));
    return a;
}
__device__ __forceinline__ void cp16(uint32_t s, const void* g) {
    asm volatile("cp.async.cg.shared.global [%0], [%1], 16;" :: "r"(s), "l"(g));
}
__device__ __forceinline__ void cp_commit() {
    asm volatile("cp.async.commit_group;" ::: "memory");
}
__device__ __forceinline__ void cp_wait2() {
    asm volatile("cp.async.wait_group 2;" ::: "memory");
}
__device__ __forceinline__ void cp_wait1() {
    asm volatile("cp.async.wait_group 1;" ::: "memory");
}
__device__ __forceinline__ void cp_wait0() {
    asm volatile("cp.async.wait_group 0;" ::: "memory");
}
__device__ __forceinline__ void mma_f16(float* c, const uint32_t* a, const uint32_t* b) {
    asm volatile(
        "mma.sync.aligned.m16n8k16.row.col.f32.f16.f16.f32 "
        "{%0,%1,%2,%3}, {%4,%5,%6,%7}, {%8,%9}, {%0,%1,%2,%3};\n"
        : "+f"(c[0]), "+f"(c[1]), "+f"(c[2]), "+f"(c[3])
        : "r"(a[0]), "r"(a[1]), "r"(a[2]), "r"(a[3]),
          "r"(b[0]), "r"(b[1]));
}
__device__ __forceinline__ uint32_t pack2(float x, float y) {
    __half2 h = __floats2half2_rn(x, y);
    return *reinterpret_cast<uint32_t*>(&h);
}

// ---------------- prepass: X * sx -> fragment-packed fp16 ----------------
// tile t = ((mb*KT + kt)*2 + kt2)*8 + mt ; 16x16 tile; lane l holds 8 halves:
// {A[r][k],A[r][k+1], A[r+8][k],A[r+8][k+1], A[r][k+8],A[r][k+9], A[r+8][k+8],A[r+8][k+9]}
// r = 16*mt + l/4 (+mb*BM), k = kt*32 + kt2*16 + 2*(l%4)
__global__ void prep_x(const float* __restrict__ X, const float* __restrict__ SX) {
    const int tiles = MB * KT * 2 * 8;   // 131072
    const int lane = threadIdx.x & 31;
    const int gw = (blockIdx.x * blockDim.x + threadIdx.x) >> 5;
    const int nw = (gridDim.x * blockDim.x) >> 5;
    for (int t = gw; t < tiles; t += nw) {
        const int mt  = t & 7;
        const int kt2 = (t >> 3) & 1;
        const int kt  = (t >> 4) & 127;
        const int mb  = t >> 11;
        const int r = mb * BM + mt * 16 + (lane >> 2);
        const int k = kt * BK + kt2 * 16 + (lane & 3) * 2;
        const float s0 = __ldg(SX + r);
        const float s1 = __ldg(SX + r + 8);
        const float2 x00 = *reinterpret_cast<const float2*>(X + (size_t)r * KK + k);
        const float2 x10 = *reinterpret_cast<const float2*>(X + (size_t)(r + 8) * KK + k);
        const float2 x01 = *reinterpret_cast<const float2*>(X + (size_t)r * KK + k + 8);
        const float2 x11 = *reinterpret_cast<const float2*>(X + (size_t)(r + 8) * KK + k + 8);
        uint4 v;
        v.x = pack2(x00.x * s0, x00.y * s0);
        v.y = pack2(x10.x * s1, x10.y * s1);
        v.z = pack2(x01.x * s0, x01.y * s0);
        v.w = pack2(x11.x * s1, x11.y * s1);
        *reinterpret_cast<uint4*>(g_Xa + (size_t)t * 256 + lane * 8) = v;
    }
}

// ---------------- prepass: (W-off)*ws -> fragment-packed fp16 ----------------
// tile t = ((nb*KT + kt)*2 + kt2)*32 + nt ; 8x16 tile; lane l holds 4 halves:
// {B[n][k],B[n][k+1], B[n][k+8],B[n][k+9]}, n = 8*nt + l/4 (+nb*BN)
__global__ void prep_w(const float* __restrict__ W, const float* __restrict__ WS,
                       const float* __restrict__ OFF) {
    const int tiles = NB * KT * 2 * 32;  // 352256
    const int lane = threadIdx.x & 31;
    const int gw = (blockIdx.x * blockDim.x + threadIdx.x) >> 5;
    const int nw = (gridDim.x * blockDim.x) >> 5;
    for (int t = gw; t < tiles; t += nw) {
        const int nt  = t & 31;
        const int kt2 = (t >> 5) & 1;
        const int kt  = (t >> 6) & 127;
        const int nb  = t >> 13;
        const int n = nb * BN + nt * 8 + (lane >> 2);
        const int k = kt * BK + kt2 * 16 + (lane & 3) * 2;
        const int g = kt >> 2;               // whole 32-span lies in one 128-group
        const float ws  = __ldg(WS + (size_t)n * GG + g);
        const float off = __ldg(OFF + (size_t)n * GG + g);
        const float2 w0 = *reinterpret_cast<const float2*>(W + (size_t)n * KK + k);
        const float2 w1 = *reinterpret_cast<const float2*>(W + (size_t)n * KK + k + 8);
        uint2 v;
        v.x = pack2((w0.x - off) * ws, (w0.y - off) * ws);
        v.y = pack2((w1.x - off) * ws, (w1.y - off) * ws);
        *reinterpret_cast<uint2*>(g_Wb + (size_t)t * 128 + lane * 4) = v;
    }
}

// ---------------- GEMM: fragment-packed fp16 mma.sync ----------------
__global__ __launch_bounds__(THREADS, 1)
void gemm_frag(float* __restrict__ OUT) {
    extern __shared__ char smem[];
    const uint32_t sbase = smem_u32(smem);

    const int tid = threadIdx.x;
    const int wid = tid >> 5;
    const int lane = tid & 31;
    const int wm = wid >> 2;        // 0..1
    const int wn = wid & 3;         // 0..3

    // CTA swizzle: groups of 8 mb per nb sweep.
    const int bid = blockIdx.x;
    const int grp = bid / (8 * NB);
    const int rem = bid - grp * (8 * NB);
    const int mb = grp * 8 + (rem & 7);
    const int nb = rem >> 3;

    const __half* Ag = g_Xa + (size_t)mb * KT * A_HALVES;
    const __half* Bg = g_Wb + (size_t)nb * KT * B_HALVES;

    float acc[4][8][4];
    #pragma unroll
    for (int i = 0; i < 4; i++)
        #pragma unroll
        for (int j = 0; j < 8; j++)
            #pragma unroll
            for (int c = 0; c < 4; c++) acc[i][j][c] = 0.f;

    auto load_stage = [&](int s, int kt) {
        const uint32_t sa = sbase + s * STAGE_BYTES;
        const char* a = (const char*)(Ag + (size_t)kt * A_HALVES) + tid * 32;
        #pragma unroll
        for (int j = 0; j < 2; j++) cp16(sa + tid * 32 + j * 16, a + j * 16);
        const uint32_t sbb = sa + A_BYTES;
        const char* b = (const char*)(Bg + (size_t)kt * B_HALVES) + tid * 64;
        #pragma unroll
        for (int j = 0; j < 4; j++) cp16(sbb + tid * 64 + j * 16, b + j * 16);
        cp_commit();
    };

    auto compute = [&](int s) {
        const char* As = smem + s * STAGE_BYTES;
        const char* Bs = As + A_BYTES;
        #pragma unroll
        for (int kt2 = 0; kt2 < 2; kt2++) {
            uint4 af[4];
            #pragma unroll
            for (int mi = 0; mi < 4; mi++) {
                const int mt = wm * 4 + mi;
                af[mi] = *reinterpret_cast<const uint4*>(
                    As + (kt2 * 8 + mt) * 512 + lane * 16);
            }
            uint2 bf[8];
            #pragma unroll
            for (int ni = 0; ni < 8; ni++) {
                const int nt = wn * 8 + ni;
                bf[ni] = *reinterpret_cast<const uint2*>(
                    Bs + (kt2 * 32 + nt) * 256 + lane * 8);
            }
            #pragma unroll
            for (int mi = 0; mi < 4; mi++)
                #pragma unroll
                for (int ni = 0; ni < 8; ni++)
                    mma_f16(acc[mi][ni],
                            reinterpret_cast<const uint32_t*>(&af[mi]),
                            reinterpret_cast<const uint32_t*>(&bf[ni]));
        }
    };

    load_stage(0, 0);
    load_stage(1, 1);
    load_stage(2, 2);

    for (int kt = 0; kt < KT; kt++) {
        if (kt < KT - 2)       cp_wait2();
        else if (kt == KT - 2) cp_wait1();
        else                   cp_wait0();
        __syncthreads();
        if (kt + 3 < KT) load_stage((kt + 3) & 3, kt + 3);
        compute(kt & 3);
    }

    // epilogue (f32 accumulators, no further scaling)
    const int m0 = mb * BM + wm * 64;
    const int n0 = nb * BN + wn * 64;
    #pragma unroll
    for (int mi = 0; mi < 4; mi++) {
        const int row = m0 + mi * 16 + (lane >> 2);
        #pragma unroll
        for (int ni = 0; ni < 8; ni++) {
            const int col = n0 + ni * 8 + (lane & 3) * 2;
            float2 v0, v1;
            v0.x = acc[mi][ni][0]; v0.y = acc[mi][ni][1];
            v1.x = acc[mi][ni][2]; v1.y = acc[mi][ni][3];
            *reinterpret_cast<float2*>(OUT + (size_t)row * NN + col)       = v0;
            *reinterpret_cast<float2*>(OUT + (size_t)(row + 8) * NN + col) = v1;
        }
    }
}

// ---------------- launch ----------------
extern "C" void kernel_launch(void* const* d_in, const int* in_sizes, int n_in,
                              void* d_out, int out_size) {
    const float* X   = (const float*)d_in[0];
    const float* SX  = (const float*)d_in[1];
    const float* W   = (const float*)d_in[2];
    const float* WS  = (const float*)d_in[3];
    const float* OFF = (const float*)d_in[4];
    float* OUT = (float*)d_out;

    cudaFuncSetAttribute(gemm_frag,
                         cudaFuncAttributeMaxDynamicSharedMemorySize, SMEM_TOTAL);

    prep_x<<<2048, 256>>>(X, SX);
    prep_w<<<2048, 256>>>(W, WS, OFF);

    gemm_frag<<<MB * NB, THREADS, SMEM_TOTAL>>>(OUT);
}